// round 4
// baseline (speedup 1.0000x reference)
#include <cuda_runtime.h>

#define NN   20000
#define NE   160000
#define INF  16
#define H1   512
#define H2   1024
#define OUTF 16

// Scratch (device globals; float4 for guaranteed 16B alignment)
__device__ float  g_deg[NN];
__device__ float  g_dinv[NN];
__device__ float4 g_y1[NN * 4];          // [NN][16] floats: Â x
__device__ float4 g_t[NN * 4];           // [NN][16] floats: relu((Âx)W1+b1) @ Wf
__device__ float4 g_wfT[OUTF * H1 / 4];  // [16][512] floats: wfT[c][k] = (W2@Wl)[k][c]
__device__ float  g_cvec[OUTF];          // b2@Wl + bl

// ---------------------------------------------------------------- degrees
__global__ void k_deg_init() {
    int i = blockIdx.x * 256 + threadIdx.x;
    if (i < NN) g_deg[i] = 1.0f;  // self-loop
}

__global__ void k_deg(const int* __restrict__ g) {
    int e = blockIdx.x * 256 + threadIdx.x;
    if (e >= NE) return;
    int d = g[NE + e];
    atomicAdd(&g_deg[d], 1.0f);
}

__global__ void k_dinv() {
    int i = blockIdx.x * 256 + threadIdx.x;
    if (i < NN) g_dinv[i] = rsqrtf(g_deg[i]);
}

// ------------------------------------------------- layer-1 input aggregation
// init with self-loop term: y1[i] = dinv[i]^2 * x[i]
__global__ void k_y1_init(const float* __restrict__ x) {
    int idx = blockIdx.x * 256 + threadIdx.x;
    if (idx >= NN * INF) return;
    int i = idx >> 4;
    float d = g_dinv[i];
    ((float*)g_y1)[idx] = d * d * x[idx];
}

__global__ void k_agg1(const int* __restrict__ g, const float* __restrict__ x) {
    int e = blockIdx.x * 256 + threadIdx.x;
    if (e >= NE) return;
    int s = g[e];
    int d = g[NE + e];
    float nrm = g_dinv[s] * g_dinv[d];
    const float* xr = x + (size_t)s * INF;
    float* out = (float*)g_y1 + (size_t)d * INF;
#pragma unroll
    for (int q = 0; q < INF; q++) atomicAdd(out + q, nrm * xr[q]);
}

// ---------------------------------------------------- fused weight W2 @ Wl
__global__ void k_fusew(const float* __restrict__ W2, const float* __restrict__ Wl) {
    int tid = blockIdx.x * 256 + threadIdx.x;  // 8192 threads
    if (tid >= H1 * OUTF) return;
    int k = tid >> 4;
    int c = tid & 15;
    const float* w2r = W2 + (size_t)k * H2;
    float s = 0.0f;
#pragma unroll 8
    for (int j = 0; j < H2; j++) s += w2r[j] * Wl[j * OUTF + c];
    ((float*)g_wfT)[c * H1 + k] = s;  // transposed: row c contiguous in k
}

__global__ void k_cvec(const float* __restrict__ b2, const float* __restrict__ Wl,
                       const float* __restrict__ bl) {
    int c = threadIdx.x;
    if (c >= OUTF) return;
    float s = bl[c];
    for (int j = 0; j < H2; j++) s += b2[j] * Wl[j * OUTF + c];
    g_cvec[c] = s;
}

// ------------------------------------------- fused per-node MLP (warp/node)
// t[i,:] = relu(y1[i,:] @ W1 + b1) @ Wf
// lane L owns hidden units j = t*128 + L*4 + q  (t<4, q<4): float4 everywhere.
__global__ void __launch_bounds__(256) k_mlp(const float* __restrict__ W1,
                                             const float* __restrict__ b1) {
    __shared__ float4 sW1[INF * H1 / 4];  // 32 KB static: W1 row-major [16][512]

    int tid = threadIdx.x;
    const float4* W1v = (const float4*)W1;
    for (int i = tid; i < INF * H1 / 4; i += 256) sW1[i] = W1v[i];
    __syncthreads();

    int warp = tid >> 5, lane = tid & 31;
    int node = blockIdx.x * 8 + warp;   // grid = NN/8 = 2500 exactly

    // y row: 64B broadcast load
    const float4* yr = &g_y1[(size_t)node * 4];
    float4 a0 = __ldg(yr), a1 = __ldg(yr + 1), a2 = __ldg(yr + 2), a3 = __ldg(yr + 3);
    float y[16] = {a0.x, a0.y, a0.z, a0.w, a1.x, a1.y, a1.z, a1.w,
                   a2.x, a2.y, a2.z, a2.w, a3.x, a3.y, a3.z, a3.w};

    // stage 1: h[t][q] = b1[j] + sum_k y[k] * W1[k][j],  j = t*128 + lane*4 + q
    const float4* b1v = (const float4*)b1;
    float4 h[4];
#pragma unroll
    for (int t = 0; t < 4; t++) h[t] = __ldg(b1v + t * 32 + lane);

#pragma unroll
    for (int k = 0; k < 16; k++) {
        float yk = y[k];
#pragma unroll
        for (int t = 0; t < 4; t++) {
            float4 w = sW1[k * 128 + t * 32 + lane];  // conflict-free LDS.128
            h[t].x += yk * w.x; h[t].y += yk * w.y;
            h[t].z += yk * w.z; h[t].w += yk * w.w;
        }
    }
#pragma unroll
    for (int t = 0; t < 4; t++) {
        h[t].x = fmaxf(h[t].x, 0.0f); h[t].y = fmaxf(h[t].y, 0.0f);
        h[t].z = fmaxf(h[t].z, 0.0f); h[t].w = fmaxf(h[t].w, 0.0f);
    }

    // stage 2: acc[c] = sum_j h_j * wfT[c][j]   (wfT from global, L1-resident)
    float acc[16];
#pragma unroll
    for (int c = 0; c < 16; c++) acc[c] = 0.0f;
#pragma unroll
    for (int c = 0; c < 16; c++) {
#pragma unroll
        for (int t = 0; t < 4; t++) {
            float4 w = __ldg(&g_wfT[c * 128 + t * 32 + lane]);  // coalesced LDG.128
            acc[c] += h[t].x * w.x + h[t].y * w.y + h[t].z * w.z + h[t].w * w.w;
        }
    }

    // warp butterfly reduction of 16 partials
#pragma unroll
    for (int off = 16; off; off >>= 1) {
#pragma unroll
        for (int c = 0; c < 16; c++) acc[c] += __shfl_xor_sync(0xFFFFFFFFu, acc[c], off);
    }
    if (lane < 16) ((float*)g_t)[(size_t)node * OUTF + lane] = acc[lane];
}

// ------------------------------------------------- final aggregation
__global__ void k_out_init(float* __restrict__ out) {
    int idx = blockIdx.x * 256 + threadIdx.x;
    if (idx >= NN * OUTF) return;
    int i = idx >> 4;
    int c = idx & 15;
    float d = g_dinv[i];
    out[idx] = d * d * ((const float*)g_t)[idx] + g_cvec[c];
}

__global__ void k_agg2(const int* __restrict__ g, float* __restrict__ out) {
    int e = blockIdx.x * 256 + threadIdx.x;
    if (e >= NE) return;
    int s = g[e];
    int d = g[NE + e];
    float nrm = g_dinv[s] * g_dinv[d];
    const float* tr = (const float*)g_t + (size_t)s * OUTF;
    float* o = out + (size_t)d * OUTF;
#pragma unroll
    for (int q = 0; q < OUTF; q++) atomicAdd(o + q, nrm * tr[q]);
}

// ---------------------------------------------------------------- launch
extern "C" void kernel_launch(void* const* d_in, const int* in_sizes, int n_in,
                              void* d_out, int out_size) {
    const float* x   = (const float*)d_in[0];
    const int*   g   = (const int*)d_in[1];   // JAX x64-disabled: int64 -> int32
    const float* W1  = (const float*)d_in[2];
    const float* b1  = (const float*)d_in[3];
    const float* W2  = (const float*)d_in[4];
    const float* b2  = (const float*)d_in[5];
    const float* Wl  = (const float*)d_in[6];
    const float* bl  = (const float*)d_in[7];
    float* out = (float*)d_out;

    const int NB_NODE = (NN + 255) / 256;          // 79
    const int NB_EDGE = (NE + 255) / 256;          // 625
    const int NB_NF   = (NN * INF + 255) / 256;    // 1250

    k_deg_init<<<NB_NODE, 256>>>();
    k_deg<<<NB_EDGE, 256>>>(g);
    k_dinv<<<NB_NODE, 256>>>();
    k_y1_init<<<NB_NF, 256>>>(x);
    k_agg1<<<NB_EDGE, 256>>>(g, x);
    k_fusew<<<(H1 * OUTF + 255) / 256, 256>>>(W2, Wl);
    k_cvec<<<1, 32>>>(b2, Wl, bl);
    k_mlp<<<NN / 8, 256>>>(W1, b1);
    k_out_init<<<NB_NF, 256>>>(out);
    k_agg2<<<NB_EDGE, 256>>>(g, out);
}

// round 5
// speedup vs baseline: 1.0752x; 1.0752x over previous
#include <cuda_runtime.h>

#define NN   20000
#define NE   160000
#define INF  16
#define H1   512
#define H2   1024
#define OUTF 16

#define GRID 148
#define BLK  512
#define NT   (GRID * BLK)        // 75776 threads
#define WPB  (BLK / 32)          // 16 warps/block
#define NW   (GRID * WPB)        // 2368 warps

// Scratch (device globals; 128B-aligned so no two arrays share a cache line)
__device__ __align__(128) float  g_deg[NN];
__device__ __align__(128) float  g_dinv[NN];
__device__ __align__(128) float4 g_y1[NN * 4];          // [NN][16]: Â x
__device__ __align__(128) float4 g_t[NN * 4];           // [NN][16]: relu((Âx)W1+b1) @ Wf
__device__ __align__(128) float4 g_wfT[OUTF * H1 / 4];  // [16][512]: (W2@Wl)^T
__device__ __align__(128) float  g_cvec[32];            // b2@Wl + bl (padded)

// Grid barrier state: monotone counters, NEVER reset -> safe across graph replays
__device__ unsigned g_arrive[8];
__device__ unsigned g_release[8];

__device__ __forceinline__ void grid_sync(int b) {
    __syncthreads();
    if (threadIdx.x == 0) {
        __threadfence();
        unsigned old = atomicAdd(&g_arrive[b], 1u);
        unsigned target = old / (unsigned)GRID + 1u;
        if (old % (unsigned)GRID == (unsigned)(GRID - 1))
            atomicAdd(&g_release[b], 1u);
        while (*(volatile unsigned*)&g_release[b] < target) {}
        __threadfence();
    }
    __syncthreads();
}

extern "C" __global__ void __launch_bounds__(BLK, 1)
gcn_persistent(const float* __restrict__ x,  const int* __restrict__ g,
               const float* __restrict__ W1, const float* __restrict__ b1,
               const float* __restrict__ W2, const float* __restrict__ b2,
               const float* __restrict__ Wl, const float* __restrict__ bl,
               float* __restrict__ out)
{
    extern __shared__ float4 smem[];
    float4* sW1 = smem;         // [16][512] floats = 32 KB
    float4* sWf = smem + 2048;  // [16][512] floats = 32 KB

    const int tid  = threadIdx.x;
    const int gid  = blockIdx.x * BLK + tid;
    const int wid  = tid >> 5, lane = tid & 31;
    const int gw   = blockIdx.x * WPB + wid;

    // ================= S0: smem W1, deg=1 (self-loop), Wf = W2@Wl, cvec ====
    const float4* W1v = (const float4*)W1;
    for (int i = tid; i < INF * H1 / 4; i += BLK) sW1[i] = W1v[i];

    for (int i = gid; i < NN; i += NT) g_deg[i] = 1.0f;

    if (gw < H1) {  // fused weight: one warp per k-row of W2
        const int k = gw;
        float acc[16];
#pragma unroll
        for (int c = 0; c < 16; c++) acc[c] = 0.0f;
        const float* w2r = W2 + (size_t)k * H2;
#pragma unroll 4
        for (int jj = 0; jj < H2 / 32; jj++) {
            int j = jj * 32 + lane;
            float w2 = __ldg(w2r + j);
            const float4* wl = (const float4*)(Wl + (size_t)j * OUTF);
            float4 a = __ldg(wl), b = __ldg(wl + 1), c4 = __ldg(wl + 2), d4 = __ldg(wl + 3);
            acc[0]  += w2 * a.x;  acc[1]  += w2 * a.y;  acc[2]  += w2 * a.z;  acc[3]  += w2 * a.w;
            acc[4]  += w2 * b.x;  acc[5]  += w2 * b.y;  acc[6]  += w2 * b.z;  acc[7]  += w2 * b.w;
            acc[8]  += w2 * c4.x; acc[9]  += w2 * c4.y; acc[10] += w2 * c4.z; acc[11] += w2 * c4.w;
            acc[12] += w2 * d4.x; acc[13] += w2 * d4.y; acc[14] += w2 * d4.z; acc[15] += w2 * d4.w;
        }
#pragma unroll
        for (int off = 16; off; off >>= 1)
#pragma unroll
            for (int c = 0; c < 16; c++) acc[c] += __shfl_xor_sync(0xFFFFFFFFu, acc[c], off);
        if (lane < 16) ((float*)g_wfT)[lane * H1 + k] = acc[lane];
    } else if (gw == NW - 1) {  // cvec = b2 @ Wl + bl
        int c = lane & 15, half = lane >> 4;
        float s = 0.0f;
        for (int j = half * (H2 / 2); j < (half + 1) * (H2 / 2); j++)
            s += __ldg(b2 + j) * __ldg(Wl + (size_t)j * OUTF + c);
        s += __shfl_xor_sync(0xFFFFFFFFu, s, 16);
        if (lane < 16) g_cvec[c] = s + __ldg(bl + c);
    }
    grid_sync(0);

    // ================= S1: degree atomics over edges =======================
    for (int e = gid; e < NE; e += NT)
        atomicAdd(&g_deg[g[NE + e]], 1.0f);
    grid_sync(1);

    // ================= S2: dinv + y1 self-loop init ========================
    for (int i = gid; i < NN; i += NT) {
        float dv = rsqrtf(__ldcg(&g_deg[i]));  // ldcg: deg mutated by other SMs
        g_dinv[i] = dv;
        float ss = dv * dv;
        const float4* xr = (const float4*)(x + (size_t)i * INF);
#pragma unroll
        for (int q = 0; q < 4; q++) {
            float4 v = __ldg(xr + q);
            g_y1[i * 4 + q] = make_float4(ss * v.x, ss * v.y, ss * v.z, ss * v.w);
        }
    }
    grid_sync(2);

    // ================= S3: layer-1 aggregation (edge atomics) ==============
    for (int e = gid; e < NE; e += NT) {
        int s = g[e], d = g[NE + e];
        float nrm = __ldg(&g_dinv[s]) * __ldg(&g_dinv[d]);
        const float4* xr = (const float4*)(x + (size_t)s * INF);
        float* o = (float*)&g_y1[d * 4];
#pragma unroll
        for (int q = 0; q < 4; q++) {
            float4 v = __ldg(xr + q);
            atomicAdd(o + q * 4 + 0, nrm * v.x);
            atomicAdd(o + q * 4 + 1, nrm * v.y);
            atomicAdd(o + q * 4 + 2, nrm * v.z);
            atomicAdd(o + q * 4 + 3, nrm * v.w);
        }
    }
    grid_sync(3);

    // stage Wf into smem (ldcg: wfT lines were part-written by other SMs)
    for (int i = tid; i < OUTF * H1 / 4; i += BLK) sWf[i] = __ldcg(&g_wfT[i]);
    __syncthreads();

    // ================= S4: fused MLP, one warp per node ====================
    // lane L owns hidden units j = t*128 + L*4 + q  (t<4, q<4)
    const float4* b1v = (const float4*)b1;
    for (int node = gw; node < NN; node += NW) {
        float4 a0 = __ldcg(&g_y1[node * 4 + 0]), a1 = __ldcg(&g_y1[node * 4 + 1]);
        float4 a2 = __ldcg(&g_y1[node * 4 + 2]), a3 = __ldcg(&g_y1[node * 4 + 3]);
        float y[16] = {a0.x, a0.y, a0.z, a0.w, a1.x, a1.y, a1.z, a1.w,
                       a2.x, a2.y, a2.z, a2.w, a3.x, a3.y, a3.z, a3.w};

        float4 h[4];
#pragma unroll
        for (int t = 0; t < 4; t++) h[t] = __ldg(b1v + t * 32 + lane);

#pragma unroll
        for (int k = 0; k < 16; k++) {
            float yk = y[k];
#pragma unroll
            for (int t = 0; t < 4; t++) {
                float4 w = sW1[k * 128 + t * 32 + lane];  // conflict-free LDS.128
                h[t].x += yk * w.x; h[t].y += yk * w.y;
                h[t].z += yk * w.z; h[t].w += yk * w.w;
            }
        }
#pragma unroll
        for (int t = 0; t < 4; t++) {
            h[t].x = fmaxf(h[t].x, 0.0f); h[t].y = fmaxf(h[t].y, 0.0f);
            h[t].z = fmaxf(h[t].z, 0.0f); h[t].w = fmaxf(h[t].w, 0.0f);
        }

        float acc[16];
#pragma unroll
        for (int c = 0; c < 16; c++) acc[c] = 0.0f;
#pragma unroll
        for (int c = 0; c < 16; c++) {
#pragma unroll
            for (int t = 0; t < 4; t++) {
                float4 w = sWf[c * 128 + t * 32 + lane];
                acc[c] += h[t].x * w.x + h[t].y * w.y + h[t].z * w.z + h[t].w * w.w;
            }
        }
#pragma unroll
        for (int off = 16; off; off >>= 1)
#pragma unroll
            for (int c = 0; c < 16; c++) acc[c] += __shfl_xor_sync(0xFFFFFFFFu, acc[c], off);
        if (lane < 16) ((float*)g_t)[(size_t)node * OUTF + lane] = acc[lane];
    }
    grid_sync(4);

    // ================= S5: output self-loop init + bias ====================
    const float4* cv = (const float4*)g_cvec;
    for (int v = gid; v < NN * 4; v += NT) {
        int i = v >> 2, q = v & 3;
        float dv = __ldg(&g_dinv[i]);
        float ss = dv * dv;
        float4 tv = __ldcg(&g_t[v]);  // ldcg: t lines part-written cross-SM
        float4 cc = __ldg(cv + q);
        ((float4*)out)[v] = make_float4(ss * tv.x + cc.x, ss * tv.y + cc.y,
                                        ss * tv.z + cc.z, ss * tv.w + cc.w);
    }
    grid_sync(5);

    // ================= S6: layer-2 aggregation (edge atomics) ==============
    for (int e = gid; e < NE; e += NT) {
        int s = g[e], d = g[NE + e];
        float nrm = __ldg(&g_dinv[s]) * __ldg(&g_dinv[d]);
        float* o = out + (size_t)d * OUTF;
#pragma unroll
        for (int q = 0; q < 4; q++) {
            float4 v = __ldcg(&g_t[s * 4 + q]);
            atomicAdd(o + q * 4 + 0, nrm * v.x);
            atomicAdd(o + q * 4 + 1, nrm * v.y);
            atomicAdd(o + q * 4 + 2, nrm * v.z);
            atomicAdd(o + q * 4 + 3, nrm * v.w);
        }
    }
}

// ---------------------------------------------------------------- launch
extern "C" void kernel_launch(void* const* d_in, const int* in_sizes, int n_in,
                              void* d_out, int out_size) {
    const float* x  = (const float*)d_in[0];
    const int*   g  = (const int*)d_in[1];   // int64 in ref, int32 on device (JAX x64 off)
    const float* W1 = (const float*)d_in[2];
    const float* b1 = (const float*)d_in[3];
    const float* W2 = (const float*)d_in[4];
    const float* b2 = (const float*)d_in[5];
    const float* Wl = (const float*)d_in[6];
    const float* bl = (const float*)d_in[7];
    float* out = (float*)d_out;

    cudaFuncSetAttribute(gcn_persistent,
                         cudaFuncAttributeMaxDynamicSharedMemorySize, 65536);
    gcn_persistent<<<GRID, BLK, 65536>>>(x, g, W1, b1, W2, b2, Wl, bl, out);
}

// round 6
// speedup vs baseline: 1.2970x; 1.2063x over previous
#include <cuda_runtime.h>

#define NN   20000
#define NE   160000
#define INF  16
#define H1   512
#define H2   1024
#define OUTF 16

#define GRID 148
#define BLK  512
#define NT   (GRID * BLK)        // 75776 threads
#define WPB  (BLK / 32)          // 16 warps/block
#define NW   (GRID * WPB)        // 2368 warps

// Scratch (device globals)
__device__ __align__(128) float  g_deg[NN];
__device__ __align__(128) float  g_dinv[NN];
__device__ __align__(128) float4 g_xs[NN * 4];          // dinv[i] * x[i]
__device__ __align__(128) float4 g_y1[NN * 4];          // xs[self] + sum_in xs[s]
__device__ __align__(128) float4 g_t[NN * 4];           // dinv[i] * MLP(dinv[i]*y1[i])
__device__ __align__(128) float4 g_wfT[OUTF * H1 / 4];  // [16][512]: (W2@Wl)^T
__device__ __align__(128) float  g_cvec[32];            // b2@Wl + bl

// Grid barrier: monotone counters, never reset -> graph-replay safe
__device__ unsigned g_arrive[8];
__device__ unsigned g_release[8];

__device__ __forceinline__ void grid_sync(int b) {
    __syncthreads();
    if (threadIdx.x == 0) {
        __threadfence();
        unsigned old = atomicAdd(&g_arrive[b], 1u);
        unsigned target = old / (unsigned)GRID + 1u;
        if (old % (unsigned)GRID == (unsigned)(GRID - 1))
            atomicAdd(&g_release[b], 1u);
        while (*(volatile unsigned*)&g_release[b] < target) {}
        __threadfence();
    }
    __syncthreads();
}

// ---- f32x2 helpers (Blackwell packed pipe) ----
__device__ __forceinline__ unsigned long long pack2(float a) {
    unsigned long long r;
    asm("mov.b64 %0, {%1, %1};" : "=l"(r) : "f"(a));
    return r;
}
__device__ __forceinline__ unsigned long long fma2(unsigned long long a,
                                                   unsigned long long b,
                                                   unsigned long long c) {
    unsigned long long d;
    asm("fma.rn.f32x2 %0, %1, %2, %3;" : "=l"(d) : "l"(a), "l"(b), "l"(c));
    return d;
}
__device__ __forceinline__ float2 unpack2(unsigned long long v) {
    float2 f;
    asm("mov.b64 {%0, %1}, %2;" : "=f"(f.x), "=f"(f.y) : "l"(v));
    return f;
}
// vector reduction (sm_90+): 4 floats, one L2 op
__device__ __forceinline__ void redv4(float* p, float4 v) {
    asm volatile("red.global.add.v4.f32 [%0], {%1,%2,%3,%4};"
                 :: "l"(p), "f"(v.x), "f"(v.y), "f"(v.z), "f"(v.w) : "memory");
}

extern "C" __global__ void __launch_bounds__(BLK, 1)
gcn_persistent(const float* __restrict__ x,  const int* __restrict__ g,
               const float* __restrict__ W1, const float* __restrict__ b1,
               const float* __restrict__ W2, const float* __restrict__ b2,
               const float* __restrict__ Wl, const float* __restrict__ bl,
               float* __restrict__ out)
{
    extern __shared__ float4 smem[];
    float4* sW1 = smem;         // [16][512] floats = 32 KB
    float4* sWf = smem + 2048;  // [16][512] floats = 32 KB

    const int tid  = threadIdx.x;
    const int gid  = blockIdx.x * BLK + tid;
    const int wid  = tid >> 5, lane = tid & 31;
    const int gw   = blockIdx.x * WPB + wid;

    // ========== S0: stage W1, deg=1, Wf = W2@Wl (warp/k-row), cvec =========
    const float4* W1v = (const float4*)W1;
    for (int i = tid; i < INF * H1 / 4; i += BLK) sW1[i] = W1v[i];

    for (int i = gid; i < NN; i += NT) g_deg[i] = 1.0f;

    if (gw < H1) {
        const int k = gw;
        float acc[16];
#pragma unroll
        for (int c = 0; c < 16; c++) acc[c] = 0.0f;
        const float* w2r = W2 + (size_t)k * H2;
#pragma unroll 4
        for (int jj = 0; jj < H2 / 32; jj++) {
            int j = jj * 32 + lane;
            float w2 = __ldg(w2r + j);
            const float4* wl = (const float4*)(Wl + (size_t)j * OUTF);
            float4 a = __ldg(wl), b = __ldg(wl + 1), c4 = __ldg(wl + 2), d4 = __ldg(wl + 3);
            acc[0]  += w2 * a.x;  acc[1]  += w2 * a.y;  acc[2]  += w2 * a.z;  acc[3]  += w2 * a.w;
            acc[4]  += w2 * b.x;  acc[5]  += w2 * b.y;  acc[6]  += w2 * b.z;  acc[7]  += w2 * b.w;
            acc[8]  += w2 * c4.x; acc[9]  += w2 * c4.y; acc[10] += w2 * c4.z; acc[11] += w2 * c4.w;
            acc[12] += w2 * d4.x; acc[13] += w2 * d4.y; acc[14] += w2 * d4.z; acc[15] += w2 * d4.w;
        }
#pragma unroll
        for (int off = 16; off; off >>= 1)
#pragma unroll
            for (int c = 0; c < 16; c++) acc[c] += __shfl_xor_sync(0xFFFFFFFFu, acc[c], off);
        if (lane < 16) ((float*)g_wfT)[lane * H1 + k] = acc[lane];
    } else if (gw == NW - 1) {
        int c = lane & 15, half = lane >> 4;
        float s = 0.0f;
        for (int j = half * (H2 / 2); j < (half + 1) * (H2 / 2); j++)
            s += __ldg(b2 + j) * __ldg(Wl + (size_t)j * OUTF + c);
        s += __shfl_xor_sync(0xFFFFFFFFu, s, 16);
        if (lane < 16) g_cvec[c] = s + __ldg(bl + c);
    }
    grid_sync(0);

    // stage Wf into smem now (wfT stable after sync0; used after sync3)
    for (int i = tid; i < OUTF * H1 / 4; i += BLK) sWf[i] = __ldcg(&g_wfT[i]);

    // ========== S1: degree atomics ========================================
    for (int e = gid; e < NE; e += NT)
        atomicAdd(&g_deg[g[NE + e]], 1.0f);
    grid_sync(1);

    // ========== S2: dinv; xs = dinv*x; y1 = xs (self-loop) ================
    for (int i = gid; i < NN; i += NT) {
        float dv = rsqrtf(__ldcg(&g_deg[i]));
        g_dinv[i] = dv;
        const float4* xr = (const float4*)(x + (size_t)i * INF);
#pragma unroll
        for (int q = 0; q < 4; q++) {
            float4 v = __ldg(xr + q);
            float4 s = make_float4(dv * v.x, dv * v.y, dv * v.z, dv * v.w);
            g_xs[i * 4 + q] = s;
            g_y1[i * 4 + q] = s;
        }
    }
    grid_sync(2);

    // ========== S3: y1[d] += xs[s]  (vector REDs, no per-edge norm) =======
    for (int e = gid; e < NE; e += NT) {
        int s = g[e], d = g[NE + e];
        const float4* xr = &g_xs[s * 4];
        float* o = (float*)&g_y1[d * 4];
#pragma unroll
        for (int q = 0; q < 4; q++) redv4(o + q * 4, __ldcg(xr + q));
    }
    grid_sync(3);

    // ========== S4: MLP, 4 nodes/warp iteration ===========================
    // lane L owns hidden units j = t*128 + L*4 + q. y via LDG.128 + shuffle.
    const ulonglong2* b1v = (const ulonglong2*)b1;
    const ulonglong2* sW1p = (const ulonglong2*)sW1;
    for (int grp = gw; grp < NN / 4; grp += NW) {
        const int n0 = grp * 4;
        const int ln = lane & 15;
        const int myn = ln >> 2;          // which of the 4 nodes this lane carries
        float4 yv = __ldcg(&g_y1[(n0 + myn) * 4 + (ln & 3)]);
        float  dv = __ldcg(&g_dinv[n0 + myn]);
        yv.x *= dv; yv.y *= dv; yv.z *= dv; yv.w *= dv;   // y_true = dinv * y1

        // stage 1 (f32x2): h2[n][t2] over 4 nodes
        unsigned long long h2[4][8];
#pragma unroll
        for (int t = 0; t < 4; t++) {
            ulonglong2 bv = b1v[t * 32 + lane];
#pragma unroll
            for (int n = 0; n < 4; n++) { h2[n][t * 2] = bv.x; h2[n][t * 2 + 1] = bv.y; }
        }
#pragma unroll
        for (int k = 0; k < 16; k++) {
            float comp = (k & 3) == 0 ? yv.x : (k & 3) == 1 ? yv.y : (k & 3) == 2 ? yv.z : yv.w;
            unsigned long long yp[4];
#pragma unroll
            for (int n = 0; n < 4; n++)
                yp[n] = pack2(__shfl_sync(0xFFFFFFFFu, comp, n * 4 + (k >> 2)));
#pragma unroll
            for (int t = 0; t < 4; t++) {
                ulonglong2 wv = sW1p[k * 128 + t * 32 + lane];  // LDS.128
#pragma unroll
                for (int n = 0; n < 4; n++) {
                    h2[n][t * 2]     = fma2(yp[n], wv.x, h2[n][t * 2]);
                    h2[n][t * 2 + 1] = fma2(yp[n], wv.y, h2[n][t * 2 + 1]);
                }
            }
        }
        // relu -> float4 hh[node][t]
        float4 hh[4][4];
#pragma unroll
        for (int n = 0; n < 4; n++)
#pragma unroll
            for (int t = 0; t < 4; t++) {
                float2 a = unpack2(h2[n][t * 2]), b = unpack2(h2[n][t * 2 + 1]);
                hh[n][t] = make_float4(fmaxf(a.x, 0.0f), fmaxf(a.y, 0.0f),
                                       fmaxf(b.x, 0.0f), fmaxf(b.y, 0.0f));
            }

        // stage 2: two 2-node passes (register bound), scalar FMA
#pragma unroll
        for (int p = 0; p < 2; p++) {
            float acc[2][16];
#pragma unroll
            for (int m = 0; m < 2; m++)
#pragma unroll
                for (int c = 0; c < 16; c++) acc[m][c] = 0.0f;
#pragma unroll
            for (int c = 0; c < 16; c++)
#pragma unroll
                for (int t = 0; t < 4; t++) {
                    float4 w = sWf[c * 128 + t * 32 + lane];  // LDS.128, read once per pair
#pragma unroll
                    for (int m = 0; m < 2; m++) {
                        float4 h = hh[p * 2 + m][t];
                        acc[m][c] += h.x * w.x + h.y * w.y + h.z * w.z + h.w * w.w;
                    }
                }
#pragma unroll
            for (int off = 16; off; off >>= 1)
#pragma unroll
                for (int m = 0; m < 2; m++)
#pragma unroll
                    for (int c = 0; c < 16; c++)
                        acc[m][c] += __shfl_xor_sync(0xFFFFFFFFu, acc[m][c], off);
#pragma unroll
            for (int m = 0; m < 2; m++) {
                int node = n0 + p * 2 + m;
                float dvn = __shfl_sync(0xFFFFFFFFu, dv, (p * 2 + m) * 4);
                if (lane < 16) {
                    float ts = dvn * acc[m][lane];          // ts = dinv * t
                    ((float*)g_t)[(size_t)node * OUTF + lane] = ts;
                    out[(size_t)node * OUTF + lane]           = ts;  // self-loop init
                }
            }
        }
    }
    grid_sync(4);

    // ========== S6: out[d] += ts[s]  (vector REDs) ========================
    for (int e = gid; e < NE; e += NT) {
        int s = g[e], d = g[NE + e];
        const float4* tr = &g_t[s * 4];
        float* o = out + (size_t)d * OUTF;
#pragma unroll
        for (int q = 0; q < 4; q++) redv4(o + q * 4, __ldcg(tr + q));
    }
    grid_sync(5);

    // ========== S7: out = dinv[i]*out + cvec ==============================
    float4* out4 = (float4*)out;
    for (int v = gid; v < NN * 4; v += NT) {
        int i = v >> 2, q = v & 3;
        float dv = __ldcg(&g_dinv[i]);
        float4 o = __ldcg(&out4[v]);
        float4 c = __ldcg(&((const float4*)g_cvec)[q]);
        out4[v] = make_float4(dv * o.x + c.x, dv * o.y + c.y,
                              dv * o.z + c.z, dv * o.w + c.w);
    }
}

// ---------------------------------------------------------------- launch
extern "C" void kernel_launch(void* const* d_in, const int* in_sizes, int n_in,
                              void* d_out, int out_size) {
    const float* x  = (const float*)d_in[0];
    const int*   g  = (const int*)d_in[1];
    const float* W1 = (const float*)d_in[2];
    const float* b1 = (const float*)d_in[3];
    const float* W2 = (const float*)d_in[4];
    const float* b2 = (const float*)d_in[5];
    const float* Wl = (const float*)d_in[6];
    const float* bl = (const float*)d_in[7];
    float* out = (float*)d_out;

    cudaFuncSetAttribute(gcn_persistent,
                         cudaFuncAttributeMaxDynamicSharedMemorySize, 65536);
    gcn_persistent<<<GRID, BLK, 65536>>>(x, g, W1, b1, W2, b2, Wl, bl, out);
}

// round 8
// speedup vs baseline: 1.5985x; 1.2325x over previous
#include <cuda_runtime.h>

#define NN   20000
#define NE   160000
#define INF  16
#define H1   512
#define H2   1024
#define OUTF 16

#define GRID 296                 // 2 blocks per SM, all resident
#define BLK  512
#define NT   (GRID * BLK)        // 151552 threads
#define WPB  (BLK / 32)          // 16 warps/block
#define NW   (GRID * WPB)        // 4736 warps

// Scratch (device globals)
__device__ __align__(128) float  g_deg[NN];
__device__ __align__(128) float  g_dinv[NN];
__device__ __align__(128) float4 g_xs[NN * 4];          // dinv[i] * x[i]
__device__ __align__(128) float4 g_y1[NN * 4];          // xs[self] + sum_in xs[s]
__device__ __align__(128) float4 g_t[NN * 4];           // dinv[i] * MLP(dinv[i]*y1[i])
__device__ __align__(128) float4 g_wfT[OUTF * H1 / 4];  // [16][512]: (W2@Wl)^T
__device__ __align__(128) float  g_cvec[32];            // b2@Wl + bl

// Grid barrier: monotone counters, never reset -> graph-replay safe
__device__ unsigned g_arrive[8];
__device__ unsigned g_release[8];

__device__ __forceinline__ void grid_sync(int b) {
    __syncthreads();
    if (threadIdx.x == 0) {
        __threadfence();
        unsigned old = atomicAdd(&g_arrive[b], 1u);
        unsigned target = old / (unsigned)GRID + 1u;
        if (old % (unsigned)GRID == (unsigned)(GRID - 1))
            atomicAdd(&g_release[b], 1u);
        while (*(volatile unsigned*)&g_release[b] < target) {}
        __threadfence();
    }
    __syncthreads();
}

// ---- f32x2 helpers ----
__device__ __forceinline__ unsigned long long pack2(float a) {
    unsigned long long r;
    asm("mov.b64 %0, {%1, %1};" : "=l"(r) : "f"(a));
    return r;
}
__device__ __forceinline__ unsigned long long fma2(unsigned long long a,
                                                   unsigned long long b,
                                                   unsigned long long c) {
    unsigned long long d;
    asm("fma.rn.f32x2 %0, %1, %2, %3;" : "=l"(d) : "l"(a), "l"(b), "l"(c));
    return d;
}
__device__ __forceinline__ float2 unpack2(unsigned long long v) {
    float2 f;
    asm("mov.b64 {%0, %1}, %2;" : "=f"(f.x), "=f"(f.y) : "l"(v));
    return f;
}
__device__ __forceinline__ void redv4(float* p, float4 v) {
    asm volatile("red.global.add.v4.f32 [%0], {%1,%2,%3,%4};"
                 :: "l"(p), "f"(v.x), "f"(v.y), "f"(v.z), "f"(v.w) : "memory");
}

extern "C" __global__ void __launch_bounds__(BLK, 2)
gcn_persistent(const float* __restrict__ x,  const int* __restrict__ g,
               const float* __restrict__ W1, const float* __restrict__ b1,
               const float* __restrict__ W2, const float* __restrict__ b2,
               const float* __restrict__ Wl, const float* __restrict__ bl,
               float* __restrict__ out)
{
    extern __shared__ float4 smem[];
    float4* sW1 = smem;         // [16][512] floats = 32 KB
    float4* sWf = smem + 2048;  // [16][512] floats = 32 KB

    const int tid  = threadIdx.x;
    const int gid  = blockIdx.x * BLK + tid;
    const int wid  = tid >> 5, lane = tid & 31;
    const int gw   = blockIdx.x * WPB + wid;

    // ========== S0: stage W1, deg=1, Wf = W2@Wl (warp/k-row), cvec =========
    const float4* W1v = (const float4*)W1;
    for (int i = tid; i < INF * H1 / 4; i += BLK) sW1[i] = W1v[i];

    for (int i = gid; i < NN; i += NT) g_deg[i] = 1.0f;

    if (gw < H1) {
        const int k = gw;
        float acc[16];
#pragma unroll
        for (int c = 0; c < 16; c++) acc[c] = 0.0f;
        const float* w2r = W2 + (size_t)k * H2;
#pragma unroll 4
        for (int jj = 0; jj < H2 / 32; jj++) {
            int j = jj * 32 + lane;
            float w2 = __ldg(w2r + j);
            const float4* wl = (const float4*)(Wl + (size_t)j * OUTF);
            float4 a = __ldg(wl), b = __ldg(wl + 1), c4 = __ldg(wl + 2), d4 = __ldg(wl + 3);
            acc[0]  += w2 * a.x;  acc[1]  += w2 * a.y;  acc[2]  += w2 * a.z;  acc[3]  += w2 * a.w;
            acc[4]  += w2 * b.x;  acc[5]  += w2 * b.y;  acc[6]  += w2 * b.z;  acc[7]  += w2 * b.w;
            acc[8]  += w2 * c4.x; acc[9]  += w2 * c4.y; acc[10] += w2 * c4.z; acc[11] += w2 * c4.w;
            acc[12] += w2 * d4.x; acc[13] += w2 * d4.y; acc[14] += w2 * d4.z; acc[15] += w2 * d4.w;
        }
#pragma unroll
        for (int off = 16; off; off >>= 1)
#pragma unroll
            for (int c = 0; c < 16; c++) acc[c] += __shfl_xor_sync(0xFFFFFFFFu, acc[c], off);
        if (lane < 16) ((float*)g_wfT)[lane * H1 + k] = acc[lane];
    } else if (gw == NW - 1) {
        int c = lane & 15, half = lane >> 4;
        float s = 0.0f;
        for (int j = half * (H2 / 2); j < (half + 1) * (H2 / 2); j++)
            s += __ldg(b2 + j) * __ldg(Wl + (size_t)j * OUTF + c);
        s += __shfl_xor_sync(0xFFFFFFFFu, s, 16);
        if (lane < 16) g_cvec[c] = s + __ldg(bl + c);
    }
    grid_sync(0);

    // stage Wf into smem (stable after sync0; consumed after sync3)
    for (int i = tid; i < OUTF * H1 / 4; i += BLK) sWf[i] = __ldcg(&g_wfT[i]);

    // ========== S1: degree atomics ========================================
    for (int e = gid; e < NE; e += NT)
        atomicAdd(&g_deg[g[NE + e]], 1.0f);
    grid_sync(1);

    // ========== S2: dinv; xs = dinv*x; y1 = xs (self-loop) ================
    for (int i = gid; i < NN; i += NT) {
        float dv = rsqrtf(__ldcg(&g_deg[i]));
        g_dinv[i] = dv;
        const float4* xr = (const float4*)(x + (size_t)i * INF);
#pragma unroll
        for (int q = 0; q < 4; q++) {
            float4 v = __ldg(xr + q);
            float4 s = make_float4(dv * v.x, dv * v.y, dv * v.z, dv * v.w);
            g_xs[i * 4 + q] = s;
            g_y1[i * 4 + q] = s;
        }
    }
    grid_sync(2);

    // ========== S3: y1[d] += xs[s]  (vector REDs) =========================
    for (int e = gid; e < NE; e += NT) {
        int s = g[e], d = g[NE + e];
        const float4* xr = &g_xs[s * 4];
        float* o = (float*)&g_y1[d * 4];
#pragma unroll
        for (int q = 0; q < 4; q++) redv4(o + q * 4, __ldcg(xr + q));
    }
    grid_sync(3);

    // ========== S4: MLP, 2 nodes/warp iteration ===========================
    // lane L owns hidden units j = t*128 + L*4 + q (t<4,q<4); y via shuffle.
    const ulonglong2* b1v = (const ulonglong2*)b1;
    const ulonglong2* sW1p = (const ulonglong2*)sW1;
    const int ln = lane & 7;
    const int myn = ln >> 2;              // which of the 2 nodes this lane carries
    for (int grp = gw; grp < NN / 2; grp += NW) {
        const int n0 = grp * 2;
        float4 yv = __ldcg(&g_y1[(n0 + myn) * 4 + (ln & 3)]);
        float  dv = __ldcg(&g_dinv[n0 + myn]);
        yv.x *= dv; yv.y *= dv; yv.z *= dv; yv.w *= dv;   // y_true = dinv * y1

        // stage 1 (f32x2)
        unsigned long long h2[2][8];
#pragma unroll
        for (int t = 0; t < 4; t++) {
            ulonglong2 bv = b1v[t * 32 + lane];
#pragma unroll
            for (int n = 0; n < 2; n++) { h2[n][t * 2] = bv.x; h2[n][t * 2 + 1] = bv.y; }
        }
#pragma unroll
        for (int k = 0; k < 16; k++) {
            float comp = (k & 3) == 0 ? yv.x : (k & 3) == 1 ? yv.y : (k & 3) == 2 ? yv.z : yv.w;
            unsigned long long yp[2];
#pragma unroll
            for (int n = 0; n < 2; n++)
                yp[n] = pack2(__shfl_sync(0xFFFFFFFFu, comp, n * 4 + (k >> 2)));
#pragma unroll
            for (int t = 0; t < 4; t++) {
                ulonglong2 wv = sW1p[k * 128 + t * 32 + lane];  // LDS.128
#pragma unroll
                for (int n = 0; n < 2; n++) {
                    h2[n][t * 2]     = fma2(yp[n], wv.x, h2[n][t * 2]);
                    h2[n][t * 2 + 1] = fma2(yp[n], wv.y, h2[n][t * 2 + 1]);
                }
            }
        }
        // relu
        float4 hh[2][4];
#pragma unroll
        for (int n = 0; n < 2; n++)
#pragma unroll
            for (int t = 0; t < 4; t++) {
                float2 a = unpack2(h2[n][t * 2]), b = unpack2(h2[n][t * 2 + 1]);
                hh[n][t] = make_float4(fmaxf(a.x, 0.0f), fmaxf(a.y, 0.0f),
                                       fmaxf(b.x, 0.0f), fmaxf(b.y, 0.0f));
            }

        // stage 2: both nodes share each weight load
        float acc[2][16];
#pragma unroll
        for (int m = 0; m < 2; m++)
#pragma unroll
            for (int c = 0; c < 16; c++) acc[m][c] = 0.0f;
#pragma unroll
        for (int c = 0; c < 16; c++)
#pragma unroll
            for (int t = 0; t < 4; t++) {
                float4 w = sWf[c * 128 + t * 32 + lane];  // LDS.128
#pragma unroll
                for (int m = 0; m < 2; m++) {
                    float4 h = hh[m][t];
                    acc[m][c] += h.x * w.x + h.y * w.y + h.z * w.z + h.w * w.w;
                }
            }
#pragma unroll
        for (int off = 16; off; off >>= 1)
#pragma unroll
            for (int m = 0; m < 2; m++)
#pragma unroll
                for (int c = 0; c < 16; c++)
                    acc[m][c] += __shfl_xor_sync(0xFFFFFFFFu, acc[m][c], off);
#pragma unroll
        for (int m = 0; m < 2; m++) {
            int node = n0 + m;
            float dvn = __shfl_sync(0xFFFFFFFFu, dv, m * 4);
            if (lane < 16) {
                float ts = dvn * acc[m][lane];              // ts = dinv * t
                ((float*)g_t)[(size_t)node * OUTF + lane] = ts;
                out[(size_t)node * OUTF + lane]           = ts;  // self-loop init
            }
        }
    }
    grid_sync(4);

    // ========== S6: out[d] += ts[s]  (vector REDs) ========================
    for (int e = gid; e < NE; e += NT) {
        int s = g[e], d = g[NE + e];
        const float4* tr = &g_t[s * 4];
        float* o = out + (size_t)d * OUTF;
#pragma unroll
        for (int q = 0; q < 4; q++) redv4(o + q * 4, __ldcg(tr + q));
    }
    grid_sync(5);

    // ========== S7: out = dinv[i]*out + cvec ==============================
    float4* out4 = (float4*)out;
    for (int v = gid; v < NN * 4; v += NT) {
        int i = v >> 2, q = v & 3;
        float dv = __ldcg(&g_dinv[i]);
        float4 o = __ldcg(&out4[v]);
        float4 c = __ldcg(&((const float4*)g_cvec)[q]);
        out4[v] = make_float4(dv * o.x + c.x, dv * o.y + c.y,
                              dv * o.z + c.z, dv * o.w + c.w);
    }
}

// ---------------------------------------------------------------- launch
extern "C" void kernel_launch(void* const* d_in, const int* in_sizes, int n_in,
                              void* d_out, int out_size) {
    const float* x  = (const float*)d_in[0];
    const int*   g  = (const int*)d_in[1];
    const float* W1 = (const float*)d_in[2];
    const float* b1 = (const float*)d_in[3];
    const float* W2 = (const float*)d_in[4];
    const float* b2 = (const float*)d_in[5];
    const float* Wl = (const float*)d_in[6];
    const float* bl = (const float*)d_in[7];
    float* out = (float*)d_out;

    cudaFuncSetAttribute(gcn_persistent,
                         cudaFuncAttributeMaxDynamicSharedMemorySize, 65536);
    gcn_persistent<<<GRID, BLK, 65536>>>(x, g, W1, b1, W2, b2, Wl, bl, out);
}

// round 9
// speedup vs baseline: 1.8707x; 1.1703x over previous
#include <cuda_runtime.h>

#define NN   20000
#define NE   160000
#define INF  16
#define H1   512
#define H2   1024
#define OUTF 16

#define GRID 296                 // 2 blocks per SM, all resident
#define BLK  512
#define NT   (GRID * BLK)        // 151552 threads
#define WPB  (BLK / 32)          // 16 warps/block
#define NW   (GRID * WPB)        // 4736 warps

// Scratch (device globals; zero-initialized at module load)
__device__ __align__(128) float  g_deg[NN];     // zeroed at load; re-zeroed each run in S2
__device__ __align__(128) float  g_dinv[NN];
__device__ __align__(128) float4 g_xs[NN * 4];          // dinv[i] * x[i]
__device__ __align__(128) float4 g_y1[NN * 4];          // xs[self] + sum_in xs[s]
__device__ __align__(128) float4 g_t[NN * 4];           // dinv[i] * MLP(dinv[i]*y1[i])
__device__ __align__(128) float4 g_wfT[OUTF * H1 / 4];  // [16][512]: (W2@Wl)^T
__device__ __align__(128) float  g_cvec[32];            // b2@Wl + bl

// Grid barrier: monotone counters, never reset -> graph-replay safe
__device__ unsigned g_arrive[8];
__device__ unsigned g_release[8];

__device__ __forceinline__ void grid_sync(int b) {
    __syncthreads();
    if (threadIdx.x == 0) {
        __threadfence();
        unsigned old = atomicAdd(&g_arrive[b], 1u);
        unsigned target = old / (unsigned)GRID + 1u;
        if (old % (unsigned)GRID == (unsigned)(GRID - 1))
            atomicAdd(&g_release[b], 1u);
        while (*(volatile unsigned*)&g_release[b] < target) {}
        __threadfence();
    }
    __syncthreads();
}

// ---- f32x2 helpers ----
__device__ __forceinline__ unsigned long long pack2(float a) {
    unsigned long long r;
    asm("mov.b64 %0, {%1, %1};" : "=l"(r) : "f"(a));
    return r;
}
__device__ __forceinline__ unsigned long long fma2(unsigned long long a,
                                                   unsigned long long b,
                                                   unsigned long long c) {
    unsigned long long d;
    asm("fma.rn.f32x2 %0, %1, %2, %3;" : "=l"(d) : "l"(a), "l"(b), "l"(c));
    return d;
}
__device__ __forceinline__ float2 unpack2(unsigned long long v) {
    float2 f;
    asm("mov.b64 {%0, %1}, %2;" : "=f"(f.x), "=f"(f.y) : "l"(v));
    return f;
}
__device__ __forceinline__ void redv4(float* p, float4 v) {
    asm volatile("red.global.add.v4.f32 [%0], {%1,%2,%3,%4};"
                 :: "l"(p), "f"(v.x), "f"(v.y), "f"(v.z), "f"(v.w) : "memory");
}

extern "C" __global__ void __launch_bounds__(BLK, 2)
gcn_persistent(const float* __restrict__ x,  const int* __restrict__ g,
               const float* __restrict__ W1, const float* __restrict__ b1,
               const float* __restrict__ W2, const float* __restrict__ b2,
               const float* __restrict__ Wl, const float* __restrict__ bl,
               float* __restrict__ out)
{
    extern __shared__ float4 smem[];
    float4* sW1 = smem;         // [16][512] floats = 32 KB
    float4* sWf = smem + 2048;  // [16][512] floats = 32 KB

    const int tid  = threadIdx.x;
    const int gid  = blockIdx.x * BLK + tid;
    const int wid  = tid >> 5, lane = tid & 31;
    const int gw   = blockIdx.x * WPB + wid;

    // ========== S0: stage W1; deg atomics (deg starts 0); Wf=W2@Wl; cvec ===
    const float4* W1v = (const float4*)W1;
    for (int i = tid; i < INF * H1 / 4; i += BLK) sW1[i] = W1v[i];

    if (gw < H1) {  // fused weight: one warp per k-row of W2
        const int k = gw;
        float acc[16];
#pragma unroll
        for (int c = 0; c < 16; c++) acc[c] = 0.0f;
        const float* w2r = W2 + (size_t)k * H2;
#pragma unroll 4
        for (int jj = 0; jj < H2 / 32; jj++) {
            int j = jj * 32 + lane;
            float w2 = __ldg(w2r + j);
            const float4* wl = (const float4*)(Wl + (size_t)j * OUTF);
            float4 a = __ldg(wl), b = __ldg(wl + 1), c4 = __ldg(wl + 2), d4 = __ldg(wl + 3);
            acc[0]  += w2 * a.x;  acc[1]  += w2 * a.y;  acc[2]  += w2 * a.z;  acc[3]  += w2 * a.w;
            acc[4]  += w2 * b.x;  acc[5]  += w2 * b.y;  acc[6]  += w2 * b.z;  acc[7]  += w2 * b.w;
            acc[8]  += w2 * c4.x; acc[9]  += w2 * c4.y; acc[10] += w2 * c4.z; acc[11] += w2 * c4.w;
            acc[12] += w2 * d4.x; acc[13] += w2 * d4.y; acc[14] += w2 * d4.z; acc[15] += w2 * d4.w;
        }
#pragma unroll
        for (int off = 16; off; off >>= 1)
#pragma unroll
            for (int c = 0; c < 16; c++) acc[c] += __shfl_xor_sync(0xFFFFFFFFu, acc[c], off);
        if (lane < 16) ((float*)g_wfT)[lane * H1 + k] = acc[lane];
    } else if (gw == NW - 1) {
        int c = lane & 15, half = lane >> 4;
        float s = 0.0f;
        for (int j = half * (H2 / 2); j < (half + 1) * (H2 / 2); j++)
            s += __ldg(b2 + j) * __ldg(Wl + (size_t)j * OUTF + c);
        s += __shfl_xor_sync(0xFFFFFFFFu, s, 16);
        if (lane < 16) g_cvec[c] = s + __ldg(bl + c);
    }

    // degree atomics overlap with fusew (deg assumed zero at entry)
    for (int e = gid; e < NE; e += NT)
        atomicAdd(&g_deg[g[NE + e]], 1.0f);
    grid_sync(0);

    // stage Wf into smem (stable after sync0)
    for (int i = tid; i < OUTF * H1 / 4; i += BLK) sWf[i] = __ldcg(&g_wfT[i]);

    // ========== S2: dinv = rsqrt(deg+1); xs = dinv*x; y1 = xs; deg := 0 ====
    for (int i = gid; i < NN; i += NT) {
        float dv = rsqrtf(__ldcg(&g_deg[i]) + 1.0f);   // +1 = self-loop
        __stcg(&g_deg[i], 0.0f);                       // reset for next replay
        g_dinv[i] = dv;
        const float4* xr = (const float4*)(x + (size_t)i * INF);
#pragma unroll
        for (int q = 0; q < 4; q++) {
            float4 v = __ldg(xr + q);
            float4 s = make_float4(dv * v.x, dv * v.y, dv * v.z, dv * v.w);
            g_xs[i * 4 + q] = s;
            g_y1[i * 4 + q] = s;
        }
    }
    grid_sync(1);

    // ========== S3: y1[d] += xs[s]  (vector REDs) =========================
    for (int e = gid; e < NE; e += NT) {
        int s = g[e], d = g[NE + e];
        const float4* xr = &g_xs[s * 4];
        float* o = (float*)&g_y1[d * 4];
#pragma unroll
        for (int q = 0; q < 4; q++) redv4(o + q * 4, __ldcg(xr + q));
    }
    grid_sync(2);

    // ========== S4: MLP, 2 nodes/warp iteration ===========================
    // lane L owns hidden units j = t*128 + L*4 + q (t<4,q<4); y via shuffle.
    const ulonglong2* b1v = (const ulonglong2*)b1;
    const ulonglong2* sW1p = (const ulonglong2*)sW1;
    const int ln = lane & 7;
    const int myn = ln >> 2;              // which of the 2 nodes this lane carries
    for (int grp = gw; grp < NN / 2; grp += NW) {
        const int n0 = grp * 2;
        float4 yv = __ldcg(&g_y1[(n0 + myn) * 4 + (ln & 3)]);
        float  dv = __ldcg(&g_dinv[n0 + myn]);
        yv.x *= dv; yv.y *= dv; yv.z *= dv; yv.w *= dv;   // y_true = dinv * y1

        // stage 1 (f32x2)
        unsigned long long h2[2][8];
#pragma unroll
        for (int t = 0; t < 4; t++) {
            ulonglong2 bv = b1v[t * 32 + lane];
#pragma unroll
            for (int n = 0; n < 2; n++) { h2[n][t * 2] = bv.x; h2[n][t * 2 + 1] = bv.y; }
        }
#pragma unroll
        for (int k = 0; k < 16; k++) {
            float comp = (k & 3) == 0 ? yv.x : (k & 3) == 1 ? yv.y : (k & 3) == 2 ? yv.z : yv.w;
            unsigned long long yp[2];
#pragma unroll
            for (int n = 0; n < 2; n++)
                yp[n] = pack2(__shfl_sync(0xFFFFFFFFu, comp, n * 4 + (k >> 2)));
#pragma unroll
            for (int t = 0; t < 4; t++) {
                ulonglong2 wv = sW1p[k * 128 + t * 32 + lane];  // LDS.128
#pragma unroll
                for (int n = 0; n < 2; n++) {
                    h2[n][t * 2]     = fma2(yp[n], wv.x, h2[n][t * 2]);
                    h2[n][t * 2 + 1] = fma2(yp[n], wv.y, h2[n][t * 2 + 1]);
                }
            }
        }
        // relu
        float4 hh[2][4];
#pragma unroll
        for (int n = 0; n < 2; n++)
#pragma unroll
            for (int t = 0; t < 4; t++) {
                float2 a = unpack2(h2[n][t * 2]), b = unpack2(h2[n][t * 2 + 1]);
                hh[n][t] = make_float4(fmaxf(a.x, 0.0f), fmaxf(a.y, 0.0f),
                                       fmaxf(b.x, 0.0f), fmaxf(b.y, 0.0f));
            }

        // stage 2: both nodes share each weight load
        float acc[2][16];
#pragma unroll
        for (int m = 0; m < 2; m++)
#pragma unroll
            for (int c = 0; c < 16; c++) acc[m][c] = 0.0f;
#pragma unroll
        for (int c = 0; c < 16; c++)
#pragma unroll
            for (int t = 0; t < 4; t++) {
                float4 w = sWf[c * 128 + t * 32 + lane];  // LDS.128
#pragma unroll
                for (int m = 0; m < 2; m++) {
                    float4 h = hh[m][t];
                    acc[m][c] += h.x * w.x + h.y * w.y + h.z * w.z + h.w * w.w;
                }
            }

        // log-fold reduction: 31 shuffles; lane L ends with element n0*16+L
        float v[16];
        {
            int bit = (lane >> 4) & 1;   // fold node dimension
#pragma unroll
            for (int i = 0; i < 16; i++) {
                float give = bit ? acc[0][i] : acc[1][i];
                float keep = bit ? acc[1][i] : acc[0][i];
                v[i] = keep + __shfl_xor_sync(0xFFFFFFFFu, give, 16);
            }
        }
#pragma unroll
        for (int o = 8; o >= 1; o >>= 1) {   // fold c bits 3..0
            int bit = (lane / o) & 1;
#pragma unroll
            for (int i = 0; i < o; i++) {
                float give = bit ? v[i] : v[i + o];
                float keep = bit ? v[i + o] : v[i];
                v[i] = keep + __shfl_xor_sync(0xFFFFFFFFu, give, o);
            }
        }
        // scale by dinv of the node this lane's element belongs to
        float dvn = __shfl_sync(0xFFFFFFFFu, dv, (lane >> 4) << 2);
        float ts = dvn * v[0];
        ((float*)g_t)[(size_t)n0 * OUTF + lane] = ts;   // coalesced 128B
        out[(size_t)n0 * OUTF + lane]           = ts;   // self-loop init
    }
    grid_sync(3);

    // ========== S6: out[d] += ts[s]  (vector REDs) ========================
    for (int e = gid; e < NE; e += NT) {
        int s = g[e], d = g[NE + e];
        const float4* tr = &g_t[s * 4];
        float* o = out + (size_t)d * OUTF;
#pragma unroll
        for (int q = 0; q < 4; q++) redv4(o + q * 4, __ldcg(tr + q));
    }
    grid_sync(4);

    // ========== S7: out = dinv[i]*out + cvec ==============================
    float4* out4 = (float4*)out;
    for (int v4i = gid; v4i < NN * 4; v4i += NT) {
        int i = v4i >> 2, q = v4i & 3;
        float dv = __ldcg(&g_dinv[i]);
        float4 o = __ldcg(&out4[v4i]);
        float4 c = __ldcg(&((const float4*)g_cvec)[q]);
        out4[v4i] = make_float4(dv * o.x + c.x, dv * o.y + c.y,
                                dv * o.z + c.z, dv * o.w + c.w);
    }
}

// ---------------------------------------------------------------- launch
extern "C" void kernel_launch(void* const* d_in, const int* in_sizes, int n_in,
                              void* d_out, int out_size) {
    const float* x  = (const float*)d_in[0];
    const int*   g  = (const int*)d_in[1];
    const float* W1 = (const float*)d_in[2];
    const float* b1 = (const float*)d_in[3];
    const float* W2 = (const float*)d_in[4];
    const float* b2 = (const float*)d_in[5];
    const float* Wl = (const float*)d_in[6];
    const float* bl = (const float*)d_in[7];
    float* out = (float*)d_out;

    cudaFuncSetAttribute(gcn_persistent,
                         cudaFuncAttributeMaxDynamicSharedMemorySize, 65536);
    gcn_persistent<<<GRID, BLK, 65536>>>(x, g, W1, b1, W2, b2, Wl, bl, out);
}